// round 10
// baseline (speedup 1.0000x reference)
#include <cuda_runtime.h>
#include <cstdint>

#define NN 100000
#define NA 50000
#define DD 128
#define KIN 256
#define NE 600000
#define LN_EPS 1e-5f

// ---------------- scratch ----------------
__device__ __align__(16) float g_x[(size_t)NN * DD];
__device__ __align__(16) float g_y[(size_t)NN * DD];
__device__ __align__(16) float g_uout[(size_t)NN * DD];
__device__ __align__(16) float g_uin[(size_t)NN * DD];
__device__ float g_invs[NN];
__device__ float g_invt[NN];

__device__ int g_cnt_t[NN], g_cnt_s[NN];
__device__ int g_off_t[NN], g_off_s[NN];
__device__ int g_woff_t[NN], g_woff_s[NN];
__device__ int g_list_t[NE], g_list_s[NE];
__device__ int g_bsum[512];

// conv weights tf32 fragment layout: [mi(6)][pass(2)][kt(16)][nt(16)][lane(32)][reg(2)]
__device__ __align__(16) uint32_t g_bfrag[6 * 2 * 16 * 16 * 32 * 2];
// MLP weights: [kc(2)][pass(2)][kt(16)][nt(16)][lane(32)][reg(2)]
__device__ __align__(16) uint32_t g_mlpfrag[2 * 2 * 16 * 16 * 32 * 2];

// ---------------- helpers ----------------
__device__ __forceinline__ uint32_t rna_tf32(float x) {
    uint32_t r;
    asm("cvt.rna.tf32.f32 %0, %1;" : "=r"(r) : "f"(x));
    return r;
}
__device__ __forceinline__ void mma_tf32(float* d, const uint32_t* a, const uint32_t* b) {
    asm volatile(
        "mma.sync.aligned.m16n8k8.row.col.f32.tf32.tf32.f32 "
        "{%0,%1,%2,%3}, {%4,%5,%6,%7}, {%8,%9}, {%0,%1,%2,%3};"
        : "+f"(d[0]), "+f"(d[1]), "+f"(d[2]), "+f"(d[3])
        : "r"(a[0]), "r"(a[1]), "r"(a[2]), "r"(a[3]), "r"(b[0]), "r"(b[1]));
}

// ================= CSR build =================
__global__ void k_csr_zero() {
    int i = blockIdx.x * blockDim.x + threadIdx.x;
    if (i < NN) { g_cnt_t[i] = 0; g_cnt_s[i] = 0; }
}
__global__ void k_hist(const int* __restrict__ s, const int* __restrict__ t) {
    int e = blockIdx.x * blockDim.x + threadIdx.x;
    if (e < NE) {
        atomicAdd(&g_cnt_t[t[e]], 1);
        atomicAdd(&g_cnt_s[s[e]], 1);
    }
}
__global__ void __launch_bounds__(512) k_scan1() {
    __shared__ int sh[512];
    int i = blockIdx.x * 512 + threadIdx.x;
    int v = (i < NN) ? g_cnt_t[i] : 0;
    sh[threadIdx.x] = v;
    __syncthreads();
    for (int o = 256; o; o >>= 1) {
        if (threadIdx.x < o) sh[threadIdx.x] += sh[threadIdx.x + o];
        __syncthreads();
    }
    if (threadIdx.x == 0) g_bsum[blockIdx.x] = sh[0];
    __syncthreads();
    int w = (i < NN) ? g_cnt_s[i] : 0;
    sh[threadIdx.x] = w;
    __syncthreads();
    for (int o = 256; o; o >>= 1) {
        if (threadIdx.x < o) sh[threadIdx.x] += sh[threadIdx.x + o];
        __syncthreads();
    }
    if (threadIdx.x == 0) g_bsum[256 + blockIdx.x] = sh[0];
}
__global__ void __launch_bounds__(256) k_scan2(int nblk) {
    __shared__ int st[256], ss[256];
    int b = threadIdx.x;
    int vt = (b < nblk) ? g_bsum[b] : 0;
    int vs = (b < nblk) ? g_bsum[256 + b] : 0;
    st[b] = vt; ss[b] = vs;
    __syncthreads();
    for (int o = 1; o < 256; o <<= 1) {
        int at = (b >= o) ? st[b - o] : 0;
        int as = (b >= o) ? ss[b - o] : 0;
        __syncthreads();
        st[b] += at; ss[b] += as;
        __syncthreads();
    }
    if (b < nblk) {
        g_bsum[b] = st[b] - vt;
        g_bsum[256 + b] = ss[b] - vs;
    }
}
__global__ void __launch_bounds__(512) k_scan3() {
    __shared__ int st[512], ss[512];
    int tid = threadIdx.x;
    int i = blockIdx.x * 512 + tid;
    int vt = (i < NN) ? g_cnt_t[i] : 0;
    int vs = (i < NN) ? g_cnt_s[i] : 0;
    st[tid] = vt; ss[tid] = vs;
    __syncthreads();
    for (int o = 1; o < 512; o <<= 1) {
        int at = (tid >= o) ? st[tid - o] : 0;
        int as = (tid >= o) ? ss[tid - o] : 0;
        __syncthreads();
        st[tid] += at; ss[tid] += as;
        __syncthreads();
    }
    if (i < NN) {
        int et = st[tid] - vt + g_bsum[blockIdx.x];
        int es = ss[tid] - vs + g_bsum[256 + blockIdx.x];
        g_off_t[i] = et; g_woff_t[i] = et;
        g_off_s[i] = es; g_woff_s[i] = es;
        g_invt[i] = vt > 0 ? rsqrtf((float)vt) : 0.f;
        g_invs[i] = vs > 0 ? rsqrtf((float)vs) : 0.f;
    }
}
__global__ void k_fill(const int* __restrict__ s, const int* __restrict__ r,
                       const int* __restrict__ t) {
    int e = blockIdx.x * blockDim.x + threadIdx.x;
    if (e < NE) {
        int si = s[e], ri = r[e], ti = t[e];
        int pt = atomicAdd(&g_woff_t[ti], 1);
        g_list_t[pt] = si | (ri << 17);
        int ps = atomicAdd(&g_woff_s[si], 1);
        g_list_s[ps] = ti | (ri << 17);
    }
}
__global__ void k_copyB(const float* __restrict__ embB) {
    int n = NA * DD / 4;
    float4* dst = (float4*)(g_x + (size_t)NA * DD);
    const float4* src = (const float4*)embB;
    for (int i = blockIdx.x * blockDim.x + threadIdx.x; i < n;
         i += gridDim.x * blockDim.x) {
        dst[i] = src[i];
    }
}

// ================= weight pre-conversion (round-8 layout, LDG.64) ========
__global__ void k_convB(const float* __restrict__ w0, const float* __restrict__ w1,
                        const float* __restrict__ w2, const float* __restrict__ w3,
                        const float* __restrict__ w4, const float* __restrict__ w5) {
    int idx = blockIdx.x * 256 + threadIdx.x;
    if (idx >= 6 * 4096) return;
    int mi = idx >> 12;
    int e = idx & 4095;
    int o = e >> 5, c4 = e & 31;
    const float* W = (mi == 0) ? w0 : (mi == 1) ? w1 : (mi == 2) ? w2
                   : (mi == 3) ? w3 : (mi == 4) ? w4 : w5;
    float4 w = __ldg((const float4*)W + o * 32 + c4);
    int kt = c4 >> 1, j = c4 & 1, nt = o >> 3;
    float wv[4] = {w.x, w.y, w.z, w.w};
#pragma unroll
    for (int c = 0; c < 4; c++) {
        int lane = (o & 7) * 4 + c;
        uint32_t hi = rna_tf32(wv[c]);
        uint32_t lo = rna_tf32(wv[c] - __uint_as_float(hi));
        uint32_t fh = ((((mi * 2 + 0) * 16 + kt) * 16 + nt) * 32 + lane) * 2 + j;
        uint32_t fl = ((((mi * 2 + 1) * 16 + kt) * 16 + nt) * 32 + lane) * 2 + j;
        g_bfrag[fh] = hi;
        g_bfrag[fl] = lo;
    }
}
__global__ void k_convB_mlp(const float* __restrict__ W) {
    int idx = blockIdx.x * 256 + threadIdx.x;
    if (idx >= 2 * 4096) return;
    int kc = idx >> 12;
    int e = idx & 4095;
    int o = e >> 5, c4 = e & 31;
    float4 w = __ldg((const float4*)W + o * 64 + kc * 32 + c4);
    int kt = c4 >> 1, j = c4 & 1, nt = o >> 3;
    float wv[4] = {w.x, w.y, w.z, w.w};
#pragma unroll
    for (int c = 0; c < 4; c++) {
        int lane = (o & 7) * 4 + c;
        uint32_t hi = rna_tf32(wv[c]);
        uint32_t lo = rna_tf32(wv[c] - __uint_as_float(hi));
        uint32_t fh = ((((kc * 2 + 0) * 16 + kt) * 16 + nt) * 32 + lane) * 2 + j;
        uint32_t fl = ((((kc * 2 + 1) * 16 + kt) * 16 + nt) * 32 + lane) * 2 + j;
        g_mlpfrag[fh] = hi;
        g_mlpfrag[fl] = lo;
    }
}

// ================= gather-aggregate (round-8 combined form) =================
__global__ void __launch_bounds__(256) k_gather(int layer, const float* __restrict__ rel) {
    __shared__ float srel[32 * DD];
    int tid = threadIdx.x;
    for (int i = tid; i < 32 * DD; i += 256) srel[i] = rel[i];
    __syncthreads();

    int lane = tid & 31;
    int warp = tid >> 5;
    const float4* x4 = (const float4*)(layer ? g_y : g_x);

#pragma unroll
    for (int nd = 0; nd < 4; nd++) {
        int n = blockIdx.x * 32 + warp * 4 + nd;
        {
            float4 a0 = make_float4(0.f, 0.f, 0.f, 0.f);
            float4 a1 = make_float4(0.f, 0.f, 0.f, 0.f);
            int beg = g_off_t[n];
            int cnt = g_cnt_t[n];
            int j = 0;
            for (; j + 2 <= cnt; j += 2) {
                int v0 = __ldg(g_list_t + beg + j);
                int v1 = __ldg(g_list_t + beg + j + 1);
                int s0 = v0 & 131071, r0 = v0 >> 17;
                int s1 = v1 & 131071, r1 = v1 >> 17;
                float w0 = __ldg(g_invs + s0);
                float w1 = __ldg(g_invs + s1);
                float4 x0 = __ldg(x4 + (size_t)s0 * 32 + lane);
                float4 x1 = __ldg(x4 + (size_t)s1 * 32 + lane);
                float4 q0 = *(const float4*)&srel[r0 * DD + lane * 4];
                float4 q1 = *(const float4*)&srel[r1 * DD + lane * 4];
                a0.x = fmaf(w0, x0.x - q0.x, a0.x);
                a0.y = fmaf(w0, x0.y - q0.y, a0.y);
                a0.z = fmaf(w0, x0.z - q0.z, a0.z);
                a0.w = fmaf(w0, x0.w - q0.w, a0.w);
                a1.x = fmaf(w1, x1.x - q1.x, a1.x);
                a1.y = fmaf(w1, x1.y - q1.y, a1.y);
                a1.z = fmaf(w1, x1.z - q1.z, a1.z);
                a1.w = fmaf(w1, x1.w - q1.w, a1.w);
            }
            if (j < cnt) {
                int v0 = __ldg(g_list_t + beg + j);
                int s0 = v0 & 131071, r0 = v0 >> 17;
                float w0 = __ldg(g_invs + s0);
                float4 x0 = __ldg(x4 + (size_t)s0 * 32 + lane);
                float4 q0 = *(const float4*)&srel[r0 * DD + lane * 4];
                a0.x = fmaf(w0, x0.x - q0.x, a0.x);
                a0.y = fmaf(w0, x0.y - q0.y, a0.y);
                a0.z = fmaf(w0, x0.z - q0.z, a0.z);
                a0.w = fmaf(w0, x0.w - q0.w, a0.w);
            }
            float sc = g_invt[n];
            ((float4*)g_uout)[(size_t)n * 32 + lane] =
                make_float4((a0.x + a1.x) * sc, (a0.y + a1.y) * sc,
                            (a0.z + a1.z) * sc, (a0.w + a1.w) * sc);
        }
        {
            float4 a0 = make_float4(0.f, 0.f, 0.f, 0.f);
            float4 a1 = make_float4(0.f, 0.f, 0.f, 0.f);
            int beg = g_off_s[n];
            int cnt = g_cnt_s[n];
            int j = 0;
            for (; j + 2 <= cnt; j += 2) {
                int v0 = __ldg(g_list_s + beg + j);
                int v1 = __ldg(g_list_s + beg + j + 1);
                int t0 = v0 & 131071, r0 = v0 >> 17;
                int t1 = v1 & 131071, r1 = v1 >> 17;
                float w0 = __ldg(g_invt + t0);
                float w1 = __ldg(g_invt + t1);
                float4 x0 = __ldg(x4 + (size_t)t0 * 32 + lane);
                float4 x1 = __ldg(x4 + (size_t)t1 * 32 + lane);
                float4 q0 = *(const float4*)&srel[r0 * DD + lane * 4];
                float4 q1 = *(const float4*)&srel[r1 * DD + lane * 4];
                a0.x = fmaf(w0, x0.x - q0.x, a0.x);
                a0.y = fmaf(w0, x0.y - q0.y, a0.y);
                a0.z = fmaf(w0, x0.z - q0.z, a0.z);
                a0.w = fmaf(w0, x0.w - q0.w, a0.w);
                a1.x = fmaf(w1, x1.x - q1.x, a1.x);
                a1.y = fmaf(w1, x1.y - q1.y, a1.y);
                a1.z = fmaf(w1, x1.z - q1.z, a1.z);
                a1.w = fmaf(w1, x1.w - q1.w, a1.w);
            }
            if (j < cnt) {
                int v0 = __ldg(g_list_s + beg + j);
                int t0 = v0 & 131071, r0 = v0 >> 17;
                float w0 = __ldg(g_invt + t0);
                float4 x0 = __ldg(x4 + (size_t)t0 * 32 + lane);
                float4 q0 = *(const float4*)&srel[r0 * DD + lane * 4];
                a0.x = fmaf(w0, x0.x - q0.x, a0.x);
                a0.y = fmaf(w0, x0.y - q0.y, a0.y);
                a0.z = fmaf(w0, x0.z - q0.z, a0.z);
                a0.w = fmaf(w0, x0.w - q0.w, a0.w);
            }
            float sc = g_invs[n];
            ((float4*)g_uin)[(size_t)n * 32 + lane] =
                make_float4((a0.x + a1.x) * sc, (a0.y + a1.y) * sc,
                            (a0.z + a1.z) * sc, (a0.w + a1.w) * sc);
        }
    }
}

// ================= mma-tile constants (64-row tile) =================
#define PADKT 516                   // 64 rows x 8 k + 4 pad
#define SM_POFF 8512                // epi = 64*133 floats
#define SMF_MMA ((8512 + 384) * 4)  // 35584 B
#define EPS_T 133

// ================= MLP via tf32 mma.sync (64-row tile, 3 CTA/SM) ==========
__global__ void __launch_bounds__(256, 3) k_mlp_mma(const float* __restrict__ X,
                                                    const float* __restrict__ bias) {
    extern __shared__ float sm[];
    uint32_t* Au = (uint32_t*)sm;
    float* spar = sm + SM_POFF;

    int tid = threadIdx.x;
    int lane = tid & 31;
    int wid = tid >> 5;
    int wm = wid & 1, wn = wid >> 1;
    int row0 = blockIdx.x * 64;

    if (tid < 128) spar[tid] = bias[tid];

    float acc[2][4][4];
#pragma unroll
    for (int i = 0; i < 2; i++)
#pragma unroll
        for (int j = 0; j < 4; j++)
#pragma unroll
            for (int c = 0; c < 4; c++) acc[i][j][c] = 0.f;

    for (int kc = 0; kc < 2; kc++) {
        __syncthreads();
        for (int idx = tid; idx < 64 * 32; idx += 256) {
            int r = idx >> 5, c4 = idx & 31;
            int row = row0 + r;
            float4 v = make_float4(0.f, 0.f, 0.f, 0.f);
            if (row < NA) v = __ldg((const float4*)X + (size_t)row * 64 + kc * 32 + c4);
            int kt = c4 >> 1;
            int mt = r >> 4;
            int jb = (c4 & 1) * 2 + ((r & 15) >> 3);
            uint32_t base = kt * PADKT + mt * 128 + (r & 7) * 16 + jb;
            Au[base + 0] = rna_tf32(v.x);
            Au[base + 4] = rna_tf32(v.y);
            Au[base + 8] = rna_tf32(v.z);
            Au[base + 12] = rna_tf32(v.w);
        }
        __syncthreads();

#pragma unroll
        for (int pass = 0; pass < 2; pass++) {
            const uint32_t* bf = g_mlpfrag + (size_t)(kc * 2 + pass) * 16384;
#pragma unroll 4
            for (int kt = 0; kt < 16; kt++) {
                uint32_t a[2][4], b[4][2];
#pragma unroll
                for (int i = 0; i < 2; i++) {
                    uint4 t = *(const uint4*)&Au[kt * PADKT + (wm * 2 + i) * 128 + lane * 4];
                    a[i][0] = t.x; a[i][1] = t.y; a[i][2] = t.z; a[i][3] = t.w;
                }
#pragma unroll
                for (int i = 0; i < 4; i++) {
                    uint2 t = __ldg((const uint2*)&bf[((kt * 16 + wn * 4 + i) * 32 + lane) * 2]);
                    b[i][0] = t.x; b[i][1] = t.y;
                }
#pragma unroll
                for (int i = 0; i < 2; i++)
#pragma unroll
                    for (int j = 0; j < 4; j++) mma_tf32(acc[i][j], a[i], b[j]);
            }
        }
    }

    __syncthreads();
    float* epi = sm;
#pragma unroll
    for (int i = 0; i < 2; i++) {
#pragma unroll
        for (int j = 0; j < 4; j++) {
            int row = wm * 32 + i * 16 + (lane >> 2);
            int col = wn * 32 + j * 8 + (lane & 3) * 2;
            epi[row * EPS_T + col] = acc[i][j][0];
            epi[row * EPS_T + col + 1] = acc[i][j][1];
            epi[(row + 8) * EPS_T + col] = acc[i][j][2];
            epi[(row + 8) * EPS_T + col + 1] = acc[i][j][3];
        }
    }
    __syncthreads();

    for (int idx = tid; idx < 64 * 32; idx += 256) {
        int r = idx >> 5, c4 = idx & 31;
        int row = row0 + r;
        if (row < NA) {
            const float* p = &epi[r * EPS_T + c4 * 4];
            const float* bb = &spar[c4 * 4];
            ((float4*)g_x)[(size_t)row * 32 + c4] =
                make_float4(p[0] + bb[0], p[1] + bb[1], p[2] + bb[2], p[3] + bb[3]);
        }
    }
}

// ================= fused conv via tf32 mma.sync (64-row tile, 3 CTA/SM) ===
__global__ void __launch_bounds__(256, 3) k_fused_mma(
    int layer, const float* __restrict__ loop_rel,
    const float* __restrict__ bias, const float* __restrict__ lng,
    const float* __restrict__ lnb, float* __restrict__ dout) {
    extern __shared__ float sm[];
    uint32_t* Au = (uint32_t*)sm;
    float* spar = sm + SM_POFF;

    int tid = threadIdx.x;
    int lane = tid & 31;
    int wid = tid >> 5;
    int wm = wid & 1, wn = wid >> 1;
    int row0 = blockIdx.x * 64;

    const float4* x4 = (const float4*)(layer ? g_y : g_x);
    float* out = layer ? dout : g_y;

    if (tid < 128) {
        spar[tid] = bias[tid];
        spar[128 + tid] = lng[tid];
        spar[256 + tid] = lnb[tid];
    }

    float acc[2][4][4];
#pragma unroll
    for (int i = 0; i < 2; i++)
#pragma unroll
        for (int j = 0; j < 4; j++)
#pragma unroll
            for (int c = 0; c < 4; c++) acc[i][j][c] = 0.f;

    for (int m = 0; m < 3; m++) {
        __syncthreads();
        for (int idx = tid; idx < 64 * 32; idx += 256) {
            int r = idx >> 5, c4 = idx & 31;
            int node = row0 + r;
            float4 v = make_float4(0.f, 0.f, 0.f, 0.f);
            if (node < NN) {
                if (m == 0) v = ((const float4*)g_uout)[(size_t)node * 32 + c4];
                else if (m == 1) v = ((const float4*)g_uin)[(size_t)node * 32 + c4];
                else {
                    float4 u = x4[(size_t)node * 32 + c4];
                    float4 lr = __ldg((const float4*)loop_rel + c4);
                    v = make_float4(u.x - lr.x, u.y - lr.y, u.z - lr.z, u.w - lr.w);
                }
            }
            int kt = c4 >> 1;
            int mt = r >> 4;
            int jb = (c4 & 1) * 2 + ((r & 15) >> 3);
            uint32_t base = kt * PADKT + mt * 128 + (r & 7) * 16 + jb;
            Au[base + 0] = rna_tf32(v.x);
            Au[base + 4] = rna_tf32(v.y);
            Au[base + 8] = rna_tf32(v.z);
            Au[base + 12] = rna_tf32(v.w);
        }
        __syncthreads();

        int mi = layer * 3 + m;
#pragma unroll
        for (int pass = 0; pass < 2; pass++) {
            const uint32_t* bf = g_bfrag + (size_t)(mi * 2 + pass) * 16384;
#pragma unroll 4
            for (int kt = 0; kt < 16; kt++) {
                uint32_t a[2][4], b[4][2];
#pragma unroll
                for (int i = 0; i < 2; i++) {
                    uint4 t = *(const uint4*)&Au[kt * PADKT + (wm * 2 + i) * 128 + lane * 4];
                    a[i][0] = t.x; a[i][1] = t.y; a[i][2] = t.z; a[i][3] = t.w;
                }
#pragma unroll
                for (int i = 0; i < 4; i++) {
                    uint2 t = __ldg((const uint2*)&bf[((kt * 16 + wn * 4 + i) * 32 + lane) * 2]);
                    b[i][0] = t.x; b[i][1] = t.y;
                }
#pragma unroll
                for (int i = 0; i < 2; i++)
#pragma unroll
                    for (int j = 0; j < 4; j++) mma_tf32(acc[i][j], a[i], b[j]);
            }
        }
    }

    // ---- epilogue: acc -> smem, 4-threads-per-row LN, coalesced store ----
    __syncthreads();
    float* epi = sm;
#pragma unroll
    for (int i = 0; i < 2; i++) {
#pragma unroll
        for (int j = 0; j < 4; j++) {
            int row = wm * 32 + i * 16 + (lane >> 2);
            int col = wn * 32 + j * 8 + (lane & 3) * 2;
            epi[row * EPS_T + col] = acc[i][j][0];
            epi[row * EPS_T + col + 1] = acc[i][j][1];
            epi[(row + 8) * EPS_T + col] = acc[i][j][2];
            epi[(row + 8) * EPS_T + col + 1] = acc[i][j][3];
        }
    }
    __syncthreads();

    const float inv3 = 1.f / 3.f;
    const float invD = 1.f / 128.f;
    {
        int r = tid >> 2;          // row 0..63
        int h = (tid & 3) * 32;    // column quarter
        float s1 = 0.f, s2 = 0.f;
#pragma unroll 4
        for (int c = h; c < h + 32; c++) {
            float v = epi[r * EPS_T + c] * inv3 + spar[c];
            if (layer == 0) v = fmaxf(v, 0.f);
            epi[r * EPS_T + c] = v;
            s1 += v;
            s2 += v * v;
        }
        s1 += __shfl_xor_sync(0xffffffff, s1, 1);
        s2 += __shfl_xor_sync(0xffffffff, s2, 1);
        s1 += __shfl_xor_sync(0xffffffff, s1, 2);
        s2 += __shfl_xor_sync(0xffffffff, s2, 2);
        float mu = s1 * invD;
        float var = fmaxf(s2 * invD - mu * mu, 0.f);
        float rstd = rsqrtf(var + LN_EPS);
#pragma unroll 4
        for (int c = h; c < h + 32; c++) {
            float v = epi[r * EPS_T + c];
            epi[r * EPS_T + c] = (v - mu) * rstd * spar[128 + c] + spar[256 + c];
        }
    }
    __syncthreads();

    for (int idx = tid; idx < 64 * 32; idx += 256) {
        int r = idx >> 5, c4 = idx & 31;
        int node = row0 + r;
        if (node < NN) {
            const float* p = &epi[r * EPS_T + c4 * 4];
            ((float4*)out)[(size_t)node * 32 + c4] =
                make_float4(p[0], p[1], p[2], p[3]);
        }
    }
}

// ================= launch =================
extern "C" void kernel_launch(void* const* d_in, const int* in_sizes, int n_in,
                              void* d_out, int out_size) {
    const float* x_typeA = (const float*)d_in[0];
    const float* W_mlp   = (const float*)d_in[1];
    const float* b_mlp   = (const float*)d_in[2];
    const float* emb_B   = (const float*)d_in[3];
    const float* rel0    = (const float*)d_in[4];
    const float* lrel0   = (const float*)d_in[5];
    const float* wloop0  = (const float*)d_in[6];
    const float* win0    = (const float*)d_in[7];
    const float* wout0   = (const float*)d_in[8];
    const float* bias0   = (const float*)d_in[9];
    const float* lng0    = (const float*)d_in[10];
    const float* lnb0    = (const float*)d_in[11];
    const float* rel1    = (const float*)d_in[12];
    const float* lrel1   = (const float*)d_in[13];
    const float* wloop1  = (const float*)d_in[14];
    const float* win1    = (const float*)d_in[15];
    const float* wout1   = (const float*)d_in[16];
    const float* bias1   = (const float*)d_in[17];
    const float* lng1    = (const float*)d_in[18];
    const float* lnb1    = (const float*)d_in[19];
    const int*   esrc    = (const int*)d_in[20];
    const int*   erel    = (const int*)d_in[21];
    const int*   edst    = (const int*)d_in[22];
    float* out = (float*)d_out;

    cudaFuncSetAttribute(k_mlp_mma, cudaFuncAttributeMaxDynamicSharedMemorySize, SMF_MMA);
    cudaFuncSetAttribute(k_fused_mma, cudaFuncAttributeMaxDynamicSharedMemorySize, SMF_MMA);

    const int nScanBlk = (NN + 511) / 512;   // 196
    const int nMmaBlk = (NN + 63) / 64;      // 1563
    const int nMlpBlk = (NA + 63) / 64;      // 782

    // launch #4 = k_mlp_mma (ncu-profiled)
    k_convB_mlp<<<(2 * 4096 + 255) / 256, 256>>>(W_mlp);
    k_csr_zero<<<(NN + 255) / 256, 256>>>();
    k_hist<<<(NE + 255) / 256, 256>>>(esrc, edst);
    k_mlp_mma<<<nMlpBlk, 256, SMF_MMA>>>(x_typeA, b_mlp);
    k_scan1<<<nScanBlk, 512>>>();
    k_scan2<<<1, 256>>>(nScanBlk);
    k_scan3<<<nScanBlk, 512>>>();
    k_fill<<<(NE + 255) / 256, 256>>>(esrc, erel, edst);
    k_copyB<<<2048, 256>>>(emb_B);
    k_convB<<<(6 * 4096 + 255) / 256, 256>>>(wout0, win0, wloop0, wout1, win1, wloop1);

    k_gather<<<NN / 32, 256>>>(0, rel0);
    k_fused_mma<<<nMmaBlk, 256, SMF_MMA>>>(0, lrel0, bias0, lng0, lnb0, out);
    k_gather<<<NN / 32, 256>>>(1, rel1);
    k_fused_mma<<<nMmaBlk, 256, SMF_MMA>>>(1, lrel1, bias1, lng1, lnb1, out);
}

// round 11
// speedup vs baseline: 1.1975x; 1.1975x over previous
#include <cuda_runtime.h>
#include <cstdint>

#define NN 100000
#define NA 50000
#define DD 128
#define KIN 256
#define NE 600000
#define LN_EPS 1e-5f

// ---------------- scratch ----------------
__device__ __align__(16) float g_x[(size_t)NN * DD];
__device__ __align__(16) float g_y[(size_t)NN * DD];
__device__ __align__(16) float g_uout[(size_t)NN * DD];
__device__ __align__(16) float g_uin[(size_t)NN * DD];
__device__ float g_invs[NN];
__device__ float g_invt[NN];

__device__ int g_cnt_t[NN], g_cnt_s[NN];
__device__ int g_off_t[NN], g_off_s[NN];
__device__ int g_woff_t[NN], g_woff_s[NN];
__device__ int g_list_t[NE], g_list_s[NE];
__device__ int g_bsum[512];

// conv weights tf32 fragment layout (hi only): [mi(6)][kt(16)][nt(16)][lane(32)][reg(2)]
__device__ __align__(16) uint32_t g_bfrag[6 * 16 * 16 * 32 * 2];
// MLP weights: [kc(2)][kt(16)][nt(16)][lane(32)][reg(2)]
__device__ __align__(16) uint32_t g_mlpfrag[2 * 16 * 16 * 32 * 2];

// ---------------- helpers ----------------
__device__ __forceinline__ uint32_t rna_tf32(float x) {
    uint32_t r;
    asm("cvt.rna.tf32.f32 %0, %1;" : "=r"(r) : "f"(x));
    return r;
}
__device__ __forceinline__ void mma_tf32(float* d, const uint32_t* a, const uint32_t* b) {
    asm volatile(
        "mma.sync.aligned.m16n8k8.row.col.f32.tf32.tf32.f32 "
        "{%0,%1,%2,%3}, {%4,%5,%6,%7}, {%8,%9}, {%0,%1,%2,%3};"
        : "+f"(d[0]), "+f"(d[1]), "+f"(d[2]), "+f"(d[3])
        : "r"(a[0]), "r"(a[1]), "r"(a[2]), "r"(a[3]), "r"(b[0]), "r"(b[1]));
}

// ================= CSR build =================
__global__ void k_csr_zero() {
    int i = blockIdx.x * blockDim.x + threadIdx.x;
    if (i < NN) { g_cnt_t[i] = 0; g_cnt_s[i] = 0; }
}
__global__ void k_hist(const int* __restrict__ s, const int* __restrict__ t) {
    int e = blockIdx.x * blockDim.x + threadIdx.x;
    if (e < NE) {
        atomicAdd(&g_cnt_t[t[e]], 1);
        atomicAdd(&g_cnt_s[s[e]], 1);
    }
}
__global__ void __launch_bounds__(512) k_scan1() {
    __shared__ int sh[512];
    int i = blockIdx.x * 512 + threadIdx.x;
    int v = (i < NN) ? g_cnt_t[i] : 0;
    sh[threadIdx.x] = v;
    __syncthreads();
    for (int o = 256; o; o >>= 1) {
        if (threadIdx.x < o) sh[threadIdx.x] += sh[threadIdx.x + o];
        __syncthreads();
    }
    if (threadIdx.x == 0) g_bsum[blockIdx.x] = sh[0];
    __syncthreads();
    int w = (i < NN) ? g_cnt_s[i] : 0;
    sh[threadIdx.x] = w;
    __syncthreads();
    for (int o = 256; o; o >>= 1) {
        if (threadIdx.x < o) sh[threadIdx.x] += sh[threadIdx.x + o];
        __syncthreads();
    }
    if (threadIdx.x == 0) g_bsum[256 + blockIdx.x] = sh[0];
}
__global__ void __launch_bounds__(256) k_scan2(int nblk) {
    __shared__ int st[256], ss[256];
    int b = threadIdx.x;
    int vt = (b < nblk) ? g_bsum[b] : 0;
    int vs = (b < nblk) ? g_bsum[256 + b] : 0;
    st[b] = vt; ss[b] = vs;
    __syncthreads();
    for (int o = 1; o < 256; o <<= 1) {
        int at = (b >= o) ? st[b - o] : 0;
        int as = (b >= o) ? ss[b - o] : 0;
        __syncthreads();
        st[b] += at; ss[b] += as;
        __syncthreads();
    }
    if (b < nblk) {
        g_bsum[b] = st[b] - vt;
        g_bsum[256 + b] = ss[b] - vs;
    }
}
__global__ void __launch_bounds__(512) k_scan3() {
    __shared__ int st[512], ss[512];
    int tid = threadIdx.x;
    int i = blockIdx.x * 512 + tid;
    int vt = (i < NN) ? g_cnt_t[i] : 0;
    int vs = (i < NN) ? g_cnt_s[i] : 0;
    st[tid] = vt; ss[tid] = vs;
    __syncthreads();
    for (int o = 1; o < 512; o <<= 1) {
        int at = (tid >= o) ? st[tid - o] : 0;
        int as = (tid >= o) ? ss[tid - o] : 0;
        __syncthreads();
        st[tid] += at; ss[tid] += as;
        __syncthreads();
    }
    if (i < NN) {
        int et = st[tid] - vt + g_bsum[blockIdx.x];
        int es = ss[tid] - vs + g_bsum[256 + blockIdx.x];
        g_off_t[i] = et; g_woff_t[i] = et;
        g_off_s[i] = es; g_woff_s[i] = es;
        g_invt[i] = vt > 0 ? rsqrtf((float)vt) : 0.f;
        g_invs[i] = vs > 0 ? rsqrtf((float)vs) : 0.f;
    }
}
__global__ void k_fill(const int* __restrict__ s, const int* __restrict__ r,
                       const int* __restrict__ t) {
    int e = blockIdx.x * blockDim.x + threadIdx.x;
    if (e < NE) {
        int si = s[e], ri = r[e], ti = t[e];
        int pt = atomicAdd(&g_woff_t[ti], 1);
        g_list_t[pt] = si | (ri << 17);
        int ps = atomicAdd(&g_woff_s[si], 1);
        g_list_s[ps] = ti | (ri << 17);
    }
}
__global__ void k_copyB(const float* __restrict__ embB) {
    int n = NA * DD / 4;
    float4* dst = (float4*)(g_x + (size_t)NA * DD);
    const float4* src = (const float4*)embB;
    for (int i = blockIdx.x * blockDim.x + threadIdx.x; i < n;
         i += gridDim.x * blockDim.x) {
        dst[i] = src[i];
    }
}

// ================= weight pre-conversion (hi-only, single pass) ==========
__global__ void k_convB(const float* __restrict__ w0, const float* __restrict__ w1,
                        const float* __restrict__ w2, const float* __restrict__ w3,
                        const float* __restrict__ w4, const float* __restrict__ w5) {
    int idx = blockIdx.x * 256 + threadIdx.x;
    if (idx >= 6 * 4096) return;
    int mi = idx >> 12;
    int e = idx & 4095;
    int o = e >> 5, c4 = e & 31;
    const float* W = (mi == 0) ? w0 : (mi == 1) ? w1 : (mi == 2) ? w2
                   : (mi == 3) ? w3 : (mi == 4) ? w4 : w5;
    float4 w = __ldg((const float4*)W + o * 32 + c4);
    int kt = c4 >> 1, j = c4 & 1, nt = o >> 3;
    float wv[4] = {w.x, w.y, w.z, w.w};
#pragma unroll
    for (int c = 0; c < 4; c++) {
        int lane = (o & 7) * 4 + c;
        uint32_t fh = (((mi * 16 + kt) * 16 + nt) * 32 + lane) * 2 + j;
        g_bfrag[fh] = rna_tf32(wv[c]);
    }
}
__global__ void k_convB_mlp(const float* __restrict__ W) {
    int idx = blockIdx.x * 256 + threadIdx.x;
    if (idx >= 2 * 4096) return;
    int kc = idx >> 12;
    int e = idx & 4095;
    int o = e >> 5, c4 = e & 31;
    float4 w = __ldg((const float4*)W + o * 64 + kc * 32 + c4);
    int kt = c4 >> 1, j = c4 & 1, nt = o >> 3;
    float wv[4] = {w.x, w.y, w.z, w.w};
#pragma unroll
    for (int c = 0; c < 4; c++) {
        int lane = (o & 7) * 4 + c;
        uint32_t fh = (((kc * 16 + kt) * 16 + nt) * 32 + lane) * 2 + j;
        g_mlpfrag[fh] = rna_tf32(wv[c]);
    }
}

// ================= gather-aggregate (round-8 combined form) =================
__global__ void __launch_bounds__(256) k_gather(int layer, const float* __restrict__ rel) {
    __shared__ float srel[32 * DD];
    int tid = threadIdx.x;
    for (int i = tid; i < 32 * DD; i += 256) srel[i] = rel[i];
    __syncthreads();

    int lane = tid & 31;
    int warp = tid >> 5;
    const float4* x4 = (const float4*)(layer ? g_y : g_x);

#pragma unroll
    for (int nd = 0; nd < 4; nd++) {
        int n = blockIdx.x * 32 + warp * 4 + nd;
        {
            float4 a0 = make_float4(0.f, 0.f, 0.f, 0.f);
            float4 a1 = make_float4(0.f, 0.f, 0.f, 0.f);
            int beg = g_off_t[n];
            int cnt = g_cnt_t[n];
            int j = 0;
            for (; j + 2 <= cnt; j += 2) {
                int v0 = __ldg(g_list_t + beg + j);
                int v1 = __ldg(g_list_t + beg + j + 1);
                int s0 = v0 & 131071, r0 = v0 >> 17;
                int s1 = v1 & 131071, r1 = v1 >> 17;
                float w0 = __ldg(g_invs + s0);
                float w1 = __ldg(g_invs + s1);
                float4 x0 = __ldg(x4 + (size_t)s0 * 32 + lane);
                float4 x1 = __ldg(x4 + (size_t)s1 * 32 + lane);
                float4 q0 = *(const float4*)&srel[r0 * DD + lane * 4];
                float4 q1 = *(const float4*)&srel[r1 * DD + lane * 4];
                a0.x = fmaf(w0, x0.x - q0.x, a0.x);
                a0.y = fmaf(w0, x0.y - q0.y, a0.y);
                a0.z = fmaf(w0, x0.z - q0.z, a0.z);
                a0.w = fmaf(w0, x0.w - q0.w, a0.w);
                a1.x = fmaf(w1, x1.x - q1.x, a1.x);
                a1.y = fmaf(w1, x1.y - q1.y, a1.y);
                a1.z = fmaf(w1, x1.z - q1.z, a1.z);
                a1.w = fmaf(w1, x1.w - q1.w, a1.w);
            }
            if (j < cnt) {
                int v0 = __ldg(g_list_t + beg + j);
                int s0 = v0 & 131071, r0 = v0 >> 17;
                float w0 = __ldg(g_invs + s0);
                float4 x0 = __ldg(x4 + (size_t)s0 * 32 + lane);
                float4 q0 = *(const float4*)&srel[r0 * DD + lane * 4];
                a0.x = fmaf(w0, x0.x - q0.x, a0.x);
                a0.y = fmaf(w0, x0.y - q0.y, a0.y);
                a0.z = fmaf(w0, x0.z - q0.z, a0.z);
                a0.w = fmaf(w0, x0.w - q0.w, a0.w);
            }
            float sc = g_invt[n];
            ((float4*)g_uout)[(size_t)n * 32 + lane] =
                make_float4((a0.x + a1.x) * sc, (a0.y + a1.y) * sc,
                            (a0.z + a1.z) * sc, (a0.w + a1.w) * sc);
        }
        {
            float4 a0 = make_float4(0.f, 0.f, 0.f, 0.f);
            float4 a1 = make_float4(0.f, 0.f, 0.f, 0.f);
            int beg = g_off_s[n];
            int cnt = g_cnt_s[n];
            int j = 0;
            for (; j + 2 <= cnt; j += 2) {
                int v0 = __ldg(g_list_s + beg + j);
                int v1 = __ldg(g_list_s + beg + j + 1);
                int t0 = v0 & 131071, r0 = v0 >> 17;
                int t1 = v1 & 131071, r1 = v1 >> 17;
                float w0 = __ldg(g_invt + t0);
                float w1 = __ldg(g_invt + t1);
                float4 x0 = __ldg(x4 + (size_t)t0 * 32 + lane);
                float4 x1 = __ldg(x4 + (size_t)t1 * 32 + lane);
                float4 q0 = *(const float4*)&srel[r0 * DD + lane * 4];
                float4 q1 = *(const float4*)&srel[r1 * DD + lane * 4];
                a0.x = fmaf(w0, x0.x - q0.x, a0.x);
                a0.y = fmaf(w0, x0.y - q0.y, a0.y);
                a0.z = fmaf(w0, x0.z - q0.z, a0.z);
                a0.w = fmaf(w0, x0.w - q0.w, a0.w);
                a1.x = fmaf(w1, x1.x - q1.x, a1.x);
                a1.y = fmaf(w1, x1.y - q1.y, a1.y);
                a1.z = fmaf(w1, x1.z - q1.z, a1.z);
                a1.w = fmaf(w1, x1.w - q1.w, a1.w);
            }
            if (j < cnt) {
                int v0 = __ldg(g_list_s + beg + j);
                int t0 = v0 & 131071, r0 = v0 >> 17;
                float w0 = __ldg(g_invt + t0);
                float4 x0 = __ldg(x4 + (size_t)t0 * 32 + lane);
                float4 q0 = *(const float4*)&srel[r0 * DD + lane * 4];
                a0.x = fmaf(w0, x0.x - q0.x, a0.x);
                a0.y = fmaf(w0, x0.y - q0.y, a0.y);
                a0.z = fmaf(w0, x0.z - q0.z, a0.z);
                a0.w = fmaf(w0, x0.w - q0.w, a0.w);
            }
            float sc = g_invs[n];
            ((float4*)g_uin)[(size_t)n * 32 + lane] =
                make_float4((a0.x + a1.x) * sc, (a0.y + a1.y) * sc,
                            (a0.z + a1.z) * sc, (a0.w + a1.w) * sc);
        }
    }
}

// ================= mma-tile constants (128-row tile, round-8 geometry) =====
#define PADKT 1028
#define SM_POFF 17024
#define SMF_MMA ((17024 + 384) * 4)
#define EPS_T 133

// ================= MLP via tf32 mma.sync (single pass) =====================
__global__ void __launch_bounds__(256, 2) k_mlp_mma(const float* __restrict__ X,
                                                    const float* __restrict__ bias) {
    extern __shared__ float sm[];
    uint32_t* Au = (uint32_t*)sm;
    float* spar = sm + SM_POFF;

    int tid = threadIdx.x;
    int lane = tid & 31;
    int wid = tid >> 5;
    int wm = wid & 1, wn = wid >> 1;
    int row0 = blockIdx.x * 128;

    if (tid < 128) spar[tid] = bias[tid];

    float acc[4][4][4];
#pragma unroll
    for (int i = 0; i < 4; i++)
#pragma unroll
        for (int j = 0; j < 4; j++)
#pragma unroll
            for (int c = 0; c < 4; c++) acc[i][j][c] = 0.f;

    for (int kc = 0; kc < 2; kc++) {
        __syncthreads();
        for (int idx = tid; idx < 128 * 32; idx += 256) {
            int r = idx >> 5, c4 = idx & 31;
            int row = row0 + r;
            float4 v = make_float4(0.f, 0.f, 0.f, 0.f);
            if (row < NA) v = __ldg((const float4*)X + (size_t)row * 64 + kc * 32 + c4);
            int kt = c4 >> 1;
            int mt = r >> 4;
            int jb = (c4 & 1) * 2 + ((r & 15) >> 3);
            uint32_t base = kt * PADKT + mt * 128 + (r & 7) * 16 + jb;
            Au[base + 0] = rna_tf32(v.x);
            Au[base + 4] = rna_tf32(v.y);
            Au[base + 8] = rna_tf32(v.z);
            Au[base + 12] = rna_tf32(v.w);
        }
        __syncthreads();

        const uint32_t* bf = g_mlpfrag + (size_t)kc * 16384;
#pragma unroll 4
        for (int kt = 0; kt < 16; kt++) {
            uint32_t a[4][4], b[4][2];
#pragma unroll
            for (int i = 0; i < 4; i++) {
                uint4 t = *(const uint4*)&Au[kt * PADKT + (wm * 4 + i) * 128 + lane * 4];
                a[i][0] = t.x; a[i][1] = t.y; a[i][2] = t.z; a[i][3] = t.w;
            }
#pragma unroll
            for (int i = 0; i < 4; i++) {
                uint2 t = __ldg((const uint2*)&bf[((kt * 16 + wn * 4 + i) * 32 + lane) * 2]);
                b[i][0] = t.x; b[i][1] = t.y;
            }
#pragma unroll
            for (int i = 0; i < 4; i++)
#pragma unroll
                for (int j = 0; j < 4; j++) mma_tf32(acc[i][j], a[i], b[j]);
        }
    }

    __syncthreads();
    float* epi = sm;
#pragma unroll
    for (int i = 0; i < 4; i++) {
#pragma unroll
        for (int j = 0; j < 4; j++) {
            int row = wm * 64 + i * 16 + (lane >> 2);
            int col = wn * 32 + j * 8 + (lane & 3) * 2;
            epi[row * EPS_T + col] = acc[i][j][0];
            epi[row * EPS_T + col + 1] = acc[i][j][1];
            epi[(row + 8) * EPS_T + col] = acc[i][j][2];
            epi[(row + 8) * EPS_T + col + 1] = acc[i][j][3];
        }
    }
    __syncthreads();

    for (int idx = tid; idx < 128 * 32; idx += 256) {
        int r = idx >> 5, c4 = idx & 31;
        int row = row0 + r;
        if (row < NA) {
            const float* p = &epi[r * EPS_T + c4 * 4];
            const float* bb = &spar[c4 * 4];
            ((float4*)g_x)[(size_t)row * 32 + c4] =
                make_float4(p[0] + bb[0], p[1] + bb[1], p[2] + bb[2], p[3] + bb[3]);
        }
    }
}

// ================= fused conv via tf32 mma.sync (single pass) ==============
__global__ void __launch_bounds__(256, 2) k_fused_mma(
    int layer, const float* __restrict__ loop_rel,
    const float* __restrict__ bias, const float* __restrict__ lng,
    const float* __restrict__ lnb, float* __restrict__ dout) {
    extern __shared__ float sm[];
    uint32_t* Au = (uint32_t*)sm;
    float* spar = sm + SM_POFF;

    int tid = threadIdx.x;
    int lane = tid & 31;
    int wid = tid >> 5;
    int wm = wid & 1, wn = wid >> 1;
    int row0 = blockIdx.x * 128;

    const float4* x4 = (const float4*)(layer ? g_y : g_x);
    float* out = layer ? dout : g_y;

    if (tid < 128) {
        spar[tid] = bias[tid];
        spar[128 + tid] = lng[tid];
        spar[256 + tid] = lnb[tid];
    }

    float acc[4][4][4];
#pragma unroll
    for (int i = 0; i < 4; i++)
#pragma unroll
        for (int j = 0; j < 4; j++)
#pragma unroll
            for (int c = 0; c < 4; c++) acc[i][j][c] = 0.f;

    for (int m = 0; m < 3; m++) {
        __syncthreads();
        for (int idx = tid; idx < 128 * 32; idx += 256) {
            int r = idx >> 5, c4 = idx & 31;
            int node = row0 + r;
            float4 v = make_float4(0.f, 0.f, 0.f, 0.f);
            if (node < NN) {
                if (m == 0) v = ((const float4*)g_uout)[(size_t)node * 32 + c4];
                else if (m == 1) v = ((const float4*)g_uin)[(size_t)node * 32 + c4];
                else {
                    float4 u = x4[(size_t)node * 32 + c4];
                    float4 lr = __ldg((const float4*)loop_rel + c4);
                    v = make_float4(u.x - lr.x, u.y - lr.y, u.z - lr.z, u.w - lr.w);
                }
            }
            int kt = c4 >> 1;
            int mt = r >> 4;
            int jb = (c4 & 1) * 2 + ((r & 15) >> 3);
            uint32_t base = kt * PADKT + mt * 128 + (r & 7) * 16 + jb;
            Au[base + 0] = rna_tf32(v.x);
            Au[base + 4] = rna_tf32(v.y);
            Au[base + 8] = rna_tf32(v.z);
            Au[base + 12] = rna_tf32(v.w);
        }
        __syncthreads();

        const uint32_t* bf = g_bfrag + (size_t)(layer * 3 + m) * 16384;
#pragma unroll 4
        for (int kt = 0; kt < 16; kt++) {
            uint32_t a[4][4], b[4][2];
#pragma unroll
            for (int i = 0; i < 4; i++) {
                uint4 t = *(const uint4*)&Au[kt * PADKT + (wm * 4 + i) * 128 + lane * 4];
                a[i][0] = t.x; a[i][1] = t.y; a[i][2] = t.z; a[i][3] = t.w;
            }
#pragma unroll
            for (int i = 0; i < 4; i++) {
                uint2 t = __ldg((const uint2*)&bf[((kt * 16 + wn * 4 + i) * 32 + lane) * 2]);
                b[i][0] = t.x; b[i][1] = t.y;
            }
#pragma unroll
            for (int i = 0; i < 4; i++)
#pragma unroll
                for (int j = 0; j < 4; j++) mma_tf32(acc[i][j], a[i], b[j]);
        }
    }

    // ---- epilogue: acc -> smem, 2-threads-per-row LN, coalesced store ----
    __syncthreads();
    float* epi = sm;
#pragma unroll
    for (int i = 0; i < 4; i++) {
#pragma unroll
        for (int j = 0; j < 4; j++) {
            int row = wm * 64 + i * 16 + (lane >> 2);
            int col = wn * 32 + j * 8 + (lane & 3) * 2;
            epi[row * EPS_T + col] = acc[i][j][0];
            epi[row * EPS_T + col + 1] = acc[i][j][1];
            epi[(row + 8) * EPS_T + col] = acc[i][j][2];
            epi[(row + 8) * EPS_T + col + 1] = acc[i][j][3];
        }
    }
    __syncthreads();

    const float inv3 = 1.f / 3.f;
    const float invD = 1.f / 128.f;
    {
        int r = tid >> 1;
        int h = (tid & 1) * 64;
        float s1 = 0.f, s2 = 0.f;
#pragma unroll 4
        for (int c = h; c < h + 64; c++) {
            float v = epi[r * EPS_T + c] * inv3 + spar[c];
            if (layer == 0) v = fmaxf(v, 0.f);
            epi[r * EPS_T + c] = v;
            s1 += v;
            s2 += v * v;
        }
        s1 += __shfl_xor_sync(0xffffffff, s1, 1);
        s2 += __shfl_xor_sync(0xffffffff, s2, 1);
        float mu = s1 * invD;
        float var = fmaxf(s2 * invD - mu * mu, 0.f);
        float rstd = rsqrtf(var + LN_EPS);
#pragma unroll 4
        for (int c = h; c < h + 64; c++) {
            float v = epi[r * EPS_T + c];
            epi[r * EPS_T + c] = (v - mu) * rstd * spar[128 + c] + spar[256 + c];
        }
    }
    __syncthreads();

    for (int idx = tid; idx < 128 * 32; idx += 256) {
        int r = idx >> 5, c4 = idx & 31;
        int node = row0 + r;
        if (node < NN) {
            const float* p = &epi[r * EPS_T + c4 * 4];
            ((float4*)out)[(size_t)node * 32 + c4] =
                make_float4(p[0], p[1], p[2], p[3]);
        }
    }
}

// ================= launch =================
extern "C" void kernel_launch(void* const* d_in, const int* in_sizes, int n_in,
                              void* d_out, int out_size) {
    const float* x_typeA = (const float*)d_in[0];
    const float* W_mlp   = (const float*)d_in[1];
    const float* b_mlp   = (const float*)d_in[2];
    const float* emb_B   = (const float*)d_in[3];
    const float* rel0    = (const float*)d_in[4];
    const float* lrel0   = (const float*)d_in[5];
    const float* wloop0  = (const float*)d_in[6];
    const float* win0    = (const float*)d_in[7];
    const float* wout0   = (const float*)d_in[8];
    const float* bias0   = (const float*)d_in[9];
    const float* lng0    = (const float*)d_in[10];
    const float* lnb0    = (const float*)d_in[11];
    const float* rel1    = (const float*)d_in[12];
    const float* lrel1   = (const float*)d_in[13];
    const float* wloop1  = (const float*)d_in[14];
    const float* win1    = (const float*)d_in[15];
    const float* wout1   = (const float*)d_in[16];
    const float* bias1   = (const float*)d_in[17];
    const float* lng1    = (const float*)d_in[18];
    const float* lnb1    = (const float*)d_in[19];
    const int*   esrc    = (const int*)d_in[20];
    const int*   erel    = (const int*)d_in[21];
    const int*   edst    = (const int*)d_in[22];
    float* out = (float*)d_out;

    cudaFuncSetAttribute(k_mlp_mma, cudaFuncAttributeMaxDynamicSharedMemorySize, SMF_MMA);
    cudaFuncSetAttribute(k_fused_mma, cudaFuncAttributeMaxDynamicSharedMemorySize, SMF_MMA);

    const int nScanBlk = (NN + 511) / 512;   // 196
    const int nMmaBlk = (NN + 127) / 128;    // 782
    const int nMlpBlk = (NA + 127) / 128;    // 391

    // launch #4 = k_mlp_mma (ncu-profiled)
    k_convB_mlp<<<(2 * 4096 + 255) / 256, 256>>>(W_mlp);
    k_csr_zero<<<(NN + 255) / 256, 256>>>();
    k_hist<<<(NE + 255) / 256, 256>>>(esrc, edst);
    k_mlp_mma<<<nMlpBlk, 256, SMF_MMA>>>(x_typeA, b_mlp);
    k_scan1<<<nScanBlk, 512>>>();
    k_scan2<<<1, 256>>>(nScanBlk);
    k_scan3<<<nScanBlk, 512>>>();
    k_fill<<<(NE + 255) / 256, 256>>>(esrc, erel, edst);
    k_copyB<<<2048, 256>>>(emb_B);
    k_convB<<<(6 * 4096 + 255) / 256, 256>>>(wout0, win0, wloop0, wout1, win1, wloop1);

    k_gather<<<NN / 32, 256>>>(0, rel0);
    k_fused_mma<<<nMmaBlk, 256, SMF_MMA>>>(0, lrel0, bias0, lng0, lnb0, out);
    k_gather<<<NN / 32, 256>>>(1, rel1);
    k_fused_mma<<<nMmaBlk, 256, SMF_MMA>>>(1, lrel1, bias1, lng1, lnb1, out);
}

// round 12
// speedup vs baseline: 1.2254x; 1.0233x over previous
#include <cuda_runtime.h>
#include <cstdint>

#define NN 100000
#define NA 50000
#define DD 128
#define KIN 256
#define NE 600000
#define LN_EPS 1e-5f

// ---------------- scratch ----------------
__device__ __align__(16) float g_x[(size_t)NN * DD];
__device__ __align__(16) float g_y[(size_t)NN * DD];
__device__ __align__(16) float g_uout[(size_t)NN * DD];
__device__ __align__(16) float g_uin[(size_t)NN * DD];
__device__ float g_invs[NN];
__device__ float g_invt[NN];

__device__ int g_cnt_t[NN], g_cnt_s[NN];
__device__ int g_off_t[NN], g_off_s[NN];
__device__ int g_woff_t[NN], g_woff_s[NN];
__device__ int g_list_t[NE], g_list_s[NE];
__device__ int g_bsum[512];

// conv weights tf32 fragment layout (hi only): [mi(6)][kt(16)][nt(16)][lane(32)][reg(2)]
__device__ __align__(16) uint32_t g_bfrag[6 * 16 * 16 * 32 * 2];
// MLP weights: [kc(2)][kt(16)][nt(16)][lane(32)][reg(2)]
__device__ __align__(16) uint32_t g_mlpfrag[2 * 16 * 16 * 32 * 2];

// ---------------- helpers ----------------
__device__ __forceinline__ uint32_t rna_tf32(float x) {
    uint32_t r;
    asm("cvt.rna.tf32.f32 %0, %1;" : "=r"(r) : "f"(x));
    return r;
}
__device__ __forceinline__ void mma_tf32(float* d, const uint32_t* a, const uint32_t* b) {
    asm volatile(
        "mma.sync.aligned.m16n8k8.row.col.f32.tf32.tf32.f32 "
        "{%0,%1,%2,%3}, {%4,%5,%6,%7}, {%8,%9}, {%0,%1,%2,%3};"
        : "+f"(d[0]), "+f"(d[1]), "+f"(d[2]), "+f"(d[3])
        : "r"(a[0]), "r"(a[1]), "r"(a[2]), "r"(a[3]), "r"(b[0]), "r"(b[1]));
}

// ================= merged prep: convB + convB_mlp + csr_zero + copyB =======
__global__ void __launch_bounds__(256) k_prep(
    const float* __restrict__ w0, const float* __restrict__ w1,
    const float* __restrict__ w2, const float* __restrict__ w3,
    const float* __restrict__ w4, const float* __restrict__ w5,
    const float* __restrict__ Wm, const float* __restrict__ embB) {
    int blk = blockIdx.x;
    int tid = threadIdx.x;
    if (blk < 96) {
        // conv weight conversion (6 matrices, hi only)
        int idx = blk * 256 + tid;
        int mi = idx >> 12;
        int e = idx & 4095;
        int o = e >> 5, c4 = e & 31;
        const float* W = (mi == 0) ? w0 : (mi == 1) ? w1 : (mi == 2) ? w2
                       : (mi == 3) ? w3 : (mi == 4) ? w4 : w5;
        float4 w = __ldg((const float4*)W + o * 32 + c4);
        int kt = c4 >> 1, j = c4 & 1, nt = o >> 3;
        float wv[4] = {w.x, w.y, w.z, w.w};
#pragma unroll
        for (int c = 0; c < 4; c++) {
            int lane = (o & 7) * 4 + c;
            g_bfrag[(((mi * 16 + kt) * 16 + nt) * 32 + lane) * 2 + j] = rna_tf32(wv[c]);
        }
    } else if (blk < 128) {
        // MLP weight conversion
        int idx = (blk - 96) * 256 + tid;
        int kc = idx >> 12;
        int e = idx & 4095;
        int o = e >> 5, c4 = e & 31;
        float4 w = __ldg((const float4*)Wm + o * 64 + kc * 32 + c4);
        int kt = c4 >> 1, j = c4 & 1, nt = o >> 3;
        float wv[4] = {w.x, w.y, w.z, w.w};
#pragma unroll
        for (int c = 0; c < 4; c++) {
            int lane = (o & 7) * 4 + c;
            g_mlpfrag[(((kc * 16 + kt) * 16 + nt) * 32 + lane) * 2 + j] = rna_tf32(wv[c]);
        }
    } else if (blk < 519) {
        // csr zero
        int i = (blk - 128) * 256 + tid;
        if (i < NN) { g_cnt_t[i] = 0; g_cnt_s[i] = 0; }
    } else {
        // copyB (1024 blocks, grid-stride)
        int n = NA * DD / 4;
        float4* dst = (float4*)(g_x + (size_t)NA * DD);
        const float4* src = (const float4*)embB;
        for (int i = (blk - 519) * 256 + tid; i < n; i += 1024 * 256) dst[i] = src[i];
    }
}

// ================= CSR build =================
__global__ void k_hist(const int* __restrict__ s, const int* __restrict__ t) {
    int e = blockIdx.x * blockDim.x + threadIdx.x;
    if (e < NE) {
        atomicAdd(&g_cnt_t[t[e]], 1);
        atomicAdd(&g_cnt_s[s[e]], 1);
    }
}
__global__ void __launch_bounds__(512) k_scan1() {
    __shared__ int sh[512];
    int i = blockIdx.x * 512 + threadIdx.x;
    int v = (i < NN) ? g_cnt_t[i] : 0;
    sh[threadIdx.x] = v;
    __syncthreads();
    for (int o = 256; o; o >>= 1) {
        if (threadIdx.x < o) sh[threadIdx.x] += sh[threadIdx.x + o];
        __syncthreads();
    }
    if (threadIdx.x == 0) g_bsum[blockIdx.x] = sh[0];
    __syncthreads();
    int w = (i < NN) ? g_cnt_s[i] : 0;
    sh[threadIdx.x] = w;
    __syncthreads();
    for (int o = 256; o; o >>= 1) {
        if (threadIdx.x < o) sh[threadIdx.x] += sh[threadIdx.x + o];
        __syncthreads();
    }
    if (threadIdx.x == 0) g_bsum[256 + blockIdx.x] = sh[0];
}
__global__ void __launch_bounds__(256) k_scan2(int nblk) {
    __shared__ int st[256], ss[256];
    int b = threadIdx.x;
    int vt = (b < nblk) ? g_bsum[b] : 0;
    int vs = (b < nblk) ? g_bsum[256 + b] : 0;
    st[b] = vt; ss[b] = vs;
    __syncthreads();
    for (int o = 1; o < 256; o <<= 1) {
        int at = (b >= o) ? st[b - o] : 0;
        int as = (b >= o) ? ss[b - o] : 0;
        __syncthreads();
        st[b] += at; ss[b] += as;
        __syncthreads();
    }
    if (b < nblk) {
        g_bsum[b] = st[b] - vt;
        g_bsum[256 + b] = ss[b] - vs;
    }
}
__global__ void __launch_bounds__(512) k_scan3() {
    __shared__ int st[512], ss[512];
    int tid = threadIdx.x;
    int i = blockIdx.x * 512 + tid;
    int vt = (i < NN) ? g_cnt_t[i] : 0;
    int vs = (i < NN) ? g_cnt_s[i] : 0;
    st[tid] = vt; ss[tid] = vs;
    __syncthreads();
    for (int o = 1; o < 512; o <<= 1) {
        int at = (tid >= o) ? st[tid - o] : 0;
        int as = (tid >= o) ? ss[tid - o] : 0;
        __syncthreads();
        st[tid] += at; ss[tid] += as;
        __syncthreads();
    }
    if (i < NN) {
        int et = st[tid] - vt + g_bsum[blockIdx.x];
        int es = ss[tid] - vs + g_bsum[256 + blockIdx.x];
        g_off_t[i] = et; g_woff_t[i] = et;
        g_off_s[i] = es; g_woff_s[i] = es;
        g_invt[i] = vt > 0 ? rsqrtf((float)vt) : 0.f;
        g_invs[i] = vs > 0 ? rsqrtf((float)vs) : 0.f;
    }
}
__global__ void k_fill(const int* __restrict__ s, const int* __restrict__ r,
                       const int* __restrict__ t) {
    int e = blockIdx.x * blockDim.x + threadIdx.x;
    if (e < NE) {
        int si = s[e], ri = r[e], ti = t[e];
        int pt = atomicAdd(&g_woff_t[ti], 1);
        g_list_t[pt] = si | (ri << 17);
        int ps = atomicAdd(&g_woff_s[si], 1);
        g_list_s[ps] = ti | (ri << 17);
    }
}

// ================= gather-aggregate =================
__global__ void __launch_bounds__(256) k_gather(int layer, const float* __restrict__ rel) {
    __shared__ float srel[32 * DD];
    int tid = threadIdx.x;
    for (int i = tid; i < 32 * DD; i += 256) srel[i] = rel[i];
    __syncthreads();

    int lane = tid & 31;
    int warp = tid >> 5;
    const float4* x4 = (const float4*)(layer ? g_y : g_x);

#pragma unroll
    for (int nd = 0; nd < 4; nd++) {
        int n = blockIdx.x * 32 + warp * 4 + nd;
        {
            float4 a0 = make_float4(0.f, 0.f, 0.f, 0.f);
            float4 a1 = make_float4(0.f, 0.f, 0.f, 0.f);
            int beg = g_off_t[n];
            int cnt = g_cnt_t[n];
            int j = 0;
            for (; j + 2 <= cnt; j += 2) {
                int v0 = __ldg(g_list_t + beg + j);
                int v1 = __ldg(g_list_t + beg + j + 1);
                int s0 = v0 & 131071, r0 = v0 >> 17;
                int s1 = v1 & 131071, r1 = v1 >> 17;
                float w0 = __ldg(g_invs + s0);
                float w1 = __ldg(g_invs + s1);
                float4 x0 = __ldg(x4 + (size_t)s0 * 32 + lane);
                float4 x1 = __ldg(x4 + (size_t)s1 * 32 + lane);
                float4 q0 = *(const float4*)&srel[r0 * DD + lane * 4];
                float4 q1 = *(const float4*)&srel[r1 * DD + lane * 4];
                a0.x = fmaf(w0, x0.x - q0.x, a0.x);
                a0.y = fmaf(w0, x0.y - q0.y, a0.y);
                a0.z = fmaf(w0, x0.z - q0.z, a0.z);
                a0.w = fmaf(w0, x0.w - q0.w, a0.w);
                a1.x = fmaf(w1, x1.x - q1.x, a1.x);
                a1.y = fmaf(w1, x1.y - q1.y, a1.y);
                a1.z = fmaf(w1, x1.z - q1.z, a1.z);
                a1.w = fmaf(w1, x1.w - q1.w, a1.w);
            }
            if (j < cnt) {
                int v0 = __ldg(g_list_t + beg + j);
                int s0 = v0 & 131071, r0 = v0 >> 17;
                float w0 = __ldg(g_invs + s0);
                float4 x0 = __ldg(x4 + (size_t)s0 * 32 + lane);
                float4 q0 = *(const float4*)&srel[r0 * DD + lane * 4];
                a0.x = fmaf(w0, x0.x - q0.x, a0.x);
                a0.y = fmaf(w0, x0.y - q0.y, a0.y);
                a0.z = fmaf(w0, x0.z - q0.z, a0.z);
                a0.w = fmaf(w0, x0.w - q0.w, a0.w);
            }
            float sc = g_invt[n];
            ((float4*)g_uout)[(size_t)n * 32 + lane] =
                make_float4((a0.x + a1.x) * sc, (a0.y + a1.y) * sc,
                            (a0.z + a1.z) * sc, (a0.w + a1.w) * sc);
        }
        {
            float4 a0 = make_float4(0.f, 0.f, 0.f, 0.f);
            float4 a1 = make_float4(0.f, 0.f, 0.f, 0.f);
            int beg = g_off_s[n];
            int cnt = g_cnt_s[n];
            int j = 0;
            for (; j + 2 <= cnt; j += 2) {
                int v0 = __ldg(g_list_s + beg + j);
                int v1 = __ldg(g_list_s + beg + j + 1);
                int t0 = v0 & 131071, r0 = v0 >> 17;
                int t1 = v1 & 131071, r1 = v1 >> 17;
                float w0 = __ldg(g_invt + t0);
                float w1 = __ldg(g_invt + t1);
                float4 x0 = __ldg(x4 + (size_t)t0 * 32 + lane);
                float4 x1 = __ldg(x4 + (size_t)t1 * 32 + lane);
                float4 q0 = *(const float4*)&srel[r0 * DD + lane * 4];
                float4 q1 = *(const float4*)&srel[r1 * DD + lane * 4];
                a0.x = fmaf(w0, x0.x - q0.x, a0.x);
                a0.y = fmaf(w0, x0.y - q0.y, a0.y);
                a0.z = fmaf(w0, x0.z - q0.z, a0.z);
                a0.w = fmaf(w0, x0.w - q0.w, a0.w);
                a1.x = fmaf(w1, x1.x - q1.x, a1.x);
                a1.y = fmaf(w1, x1.y - q1.y, a1.y);
                a1.z = fmaf(w1, x1.z - q1.z, a1.z);
                a1.w = fmaf(w1, x1.w - q1.w, a1.w);
            }
            if (j < cnt) {
                int v0 = __ldg(g_list_s + beg + j);
                int t0 = v0 & 131071, r0 = v0 >> 17;
                float w0 = __ldg(g_invt + t0);
                float4 x0 = __ldg(x4 + (size_t)t0 * 32 + lane);
                float4 q0 = *(const float4*)&srel[r0 * DD + lane * 4];
                a0.x = fmaf(w0, x0.x - q0.x, a0.x);
                a0.y = fmaf(w0, x0.y - q0.y, a0.y);
                a0.z = fmaf(w0, x0.z - q0.z, a0.z);
                a0.w = fmaf(w0, x0.w - q0.w, a0.w);
            }
            float sc = g_invs[n];
            ((float4*)g_uin)[(size_t)n * 32 + lane] =
                make_float4((a0.x + a1.x) * sc, (a0.y + a1.y) * sc,
                            (a0.z + a1.z) * sc, (a0.w + a1.w) * sc);
        }
    }
}

// ================= mma-tile constants (128-row tile) =====
#define PADKT 1028
#define SM_POFF 17024
#define SMF_MMA ((17024 + 384) * 4)
#define EPS_T 133

// b-fragment address helper
#define BF_ADDR(bf, kt, wn, jj, lane) ((const uint2*)&(bf)[(((kt) * 16 + (wn) * 4 + (jj)) * 32 + (lane)) * 2])

// ================= MLP via tf32 mma.sync (b-pipelined) =====================
__global__ void __launch_bounds__(256, 2) k_mlp_mma(const float* __restrict__ X,
                                                    const float* __restrict__ bias) {
    extern __shared__ float sm[];
    uint32_t* Au = (uint32_t*)sm;
    float* spar = sm + SM_POFF;

    int tid = threadIdx.x;
    int lane = tid & 31;
    int wid = tid >> 5;
    int wm = wid & 1, wn = wid >> 1;
    int row0 = blockIdx.x * 128;

    if (tid < 128) spar[tid] = bias[tid];

    float acc[4][4][4];
#pragma unroll
    for (int i = 0; i < 4; i++)
#pragma unroll
        for (int j = 0; j < 4; j++)
#pragma unroll
            for (int c = 0; c < 4; c++) acc[i][j][c] = 0.f;

    for (int kc = 0; kc < 2; kc++) {
        __syncthreads();
        for (int idx = tid; idx < 128 * 32; idx += 256) {
            int r = idx >> 5, c4 = idx & 31;
            int row = row0 + r;
            float4 v = make_float4(0.f, 0.f, 0.f, 0.f);
            if (row < NA) v = __ldg((const float4*)X + (size_t)row * 64 + kc * 32 + c4);
            int kt = c4 >> 1;
            int mt = r >> 4;
            int jb = (c4 & 1) * 2 + ((r & 15) >> 3);
            uint32_t base = kt * PADKT + mt * 128 + (r & 7) * 16 + jb;
            Au[base + 0] = rna_tf32(v.x);
            Au[base + 4] = rna_tf32(v.y);
            Au[base + 8] = rna_tf32(v.z);
            Au[base + 12] = rna_tf32(v.w);
        }
        __syncthreads();

        const uint32_t* bf = g_mlpfrag + (size_t)kc * 16384;
        uint2 bn0 = __ldg(BF_ADDR(bf, 0, wn, 0, lane));
        uint2 bn1 = __ldg(BF_ADDR(bf, 0, wn, 1, lane));
        uint2 bn2 = __ldg(BF_ADDR(bf, 0, wn, 2, lane));
        uint2 bn3 = __ldg(BF_ADDR(bf, 0, wn, 3, lane));
#pragma unroll
        for (int kt = 0; kt < 16; kt++) {
            uint32_t b[4][2];
            b[0][0] = bn0.x; b[0][1] = bn0.y;
            b[1][0] = bn1.x; b[1][1] = bn1.y;
            b[2][0] = bn2.x; b[2][1] = bn2.y;
            b[3][0] = bn3.x; b[3][1] = bn3.y;
            if (kt < 15) {
                bn0 = __ldg(BF_ADDR(bf, kt + 1, wn, 0, lane));
                bn1 = __ldg(BF_ADDR(bf, kt + 1, wn, 1, lane));
                bn2 = __ldg(BF_ADDR(bf, kt + 1, wn, 2, lane));
                bn3 = __ldg(BF_ADDR(bf, kt + 1, wn, 3, lane));
            }
            uint32_t a[4][4];
#pragma unroll
            for (int i = 0; i < 4; i++) {
                uint4 t = *(const uint4*)&Au[kt * PADKT + (wm * 4 + i) * 128 + lane * 4];
                a[i][0] = t.x; a[i][1] = t.y; a[i][2] = t.z; a[i][3] = t.w;
            }
#pragma unroll
            for (int i = 0; i < 4; i++)
#pragma unroll
                for (int j = 0; j < 4; j++) mma_tf32(acc[i][j], a[i], b[j]);
        }
    }

    __syncthreads();
    float* epi = sm;
#pragma unroll
    for (int i = 0; i < 4; i++) {
#pragma unroll
        for (int j = 0; j < 4; j++) {
            int row = wm * 64 + i * 16 + (lane >> 2);
            int col = wn * 32 + j * 8 + (lane & 3) * 2;
            epi[row * EPS_T + col] = acc[i][j][0];
            epi[row * EPS_T + col + 1] = acc[i][j][1];
            epi[(row + 8) * EPS_T + col] = acc[i][j][2];
            epi[(row + 8) * EPS_T + col + 1] = acc[i][j][3];
        }
    }
    __syncthreads();

    for (int idx = tid; idx < 128 * 32; idx += 256) {
        int r = idx >> 5, c4 = idx & 31;
        int row = row0 + r;
        if (row < NA) {
            const float* p = &epi[r * EPS_T + c4 * 4];
            const float* bb = &spar[c4 * 4];
            ((float4*)g_x)[(size_t)row * 32 + c4] =
                make_float4(p[0] + bb[0], p[1] + bb[1], p[2] + bb[2], p[3] + bb[3]);
        }
    }
}

// ================= fused conv via tf32 mma.sync (b-pipelined) ==============
__global__ void __launch_bounds__(256, 2) k_fused_mma(
    int layer, const float* __restrict__ loop_rel,
    const float* __restrict__ bias, const float* __restrict__ lng,
    const float* __restrict__ lnb, float* __restrict__ dout) {
    extern __shared__ float sm[];
    uint32_t* Au = (uint32_t*)sm;
    float* spar = sm + SM_POFF;

    int tid = threadIdx.x;
    int lane = tid & 31;
    int wid = tid >> 5;
    int wm = wid & 1, wn = wid >> 1;
    int row0 = blockIdx.x * 128;

    const float4* x4 = (const float4*)(layer ? g_y : g_x);
    float* out = layer ? dout : g_y;

    if (tid < 128) {
        spar[tid] = bias[tid];
        spar[128 + tid] = lng[tid];
        spar[256 + tid] = lnb[tid];
    }

    float acc[4][4][4];
#pragma unroll
    for (int i = 0; i < 4; i++)
#pragma unroll
        for (int j = 0; j < 4; j++)
#pragma unroll
            for (int c = 0; c < 4; c++) acc[i][j][c] = 0.f;

    for (int m = 0; m < 3; m++) {
        __syncthreads();
        for (int idx = tid; idx < 128 * 32; idx += 256) {
            int r = idx >> 5, c4 = idx & 31;
            int node = row0 + r;
            float4 v = make_float4(0.f, 0.f, 0.f, 0.f);
            if (node < NN) {
                if (m == 0) v = ((const float4*)g_uout)[(size_t)node * 32 + c4];
                else if (m == 1) v = ((const float4*)g_uin)[(size_t)node * 32 + c4];
                else {
                    float4 u = x4[(size_t)node * 32 + c4];
                    float4 lr = __ldg((const float4*)loop_rel + c4);
                    v = make_float4(u.x - lr.x, u.y - lr.y, u.z - lr.z, u.w - lr.w);
                }
            }
            int kt = c4 >> 1;
            int mt = r >> 4;
            int jb = (c4 & 1) * 2 + ((r & 15) >> 3);
            uint32_t base = kt * PADKT + mt * 128 + (r & 7) * 16 + jb;
            Au[base + 0] = rna_tf32(v.x);
            Au[base + 4] = rna_tf32(v.y);
            Au[base + 8] = rna_tf32(v.z);
            Au[base + 12] = rna_tf32(v.w);
        }
        __syncthreads();

        const uint32_t* bf = g_bfrag + (size_t)(layer * 3 + m) * 16384;
        uint2 bn0 = __ldg(BF_ADDR(bf, 0, wn, 0, lane));
        uint2 bn1 = __ldg(BF_ADDR(bf, 0, wn, 1, lane));
        uint2 bn2 = __ldg(BF_ADDR(bf, 0, wn, 2, lane));
        uint2 bn3 = __ldg(BF_ADDR(bf, 0, wn, 3, lane));
#pragma unroll
        for (int kt = 0; kt < 16; kt++) {
            uint32_t b[4][2];
            b[0][0] = bn0.x; b[0][1] = bn0.y;
            b[1][0] = bn1.x; b[1][1] = bn1.y;
            b[2][0] = bn2.x; b[2][1] = bn2.y;
            b[3][0] = bn3.x; b[3][1] = bn3.y;
            if (kt < 15) {
                bn0 = __ldg(BF_ADDR(bf, kt + 1, wn, 0, lane));
                bn1 = __ldg(BF_ADDR(bf, kt + 1, wn, 1, lane));
                bn2 = __ldg(BF_ADDR(bf, kt + 1, wn, 2, lane));
                bn3 = __ldg(BF_ADDR(bf, kt + 1, wn, 3, lane));
            }
            uint32_t a[4][4];
#pragma unroll
            for (int i = 0; i < 4; i++) {
                uint4 t = *(const uint4*)&Au[kt * PADKT + (wm * 4 + i) * 128 + lane * 4];
                a[i][0] = t.x; a[i][1] = t.y; a[i][2] = t.z; a[i][3] = t.w;
            }
#pragma unroll
            for (int i = 0; i < 4; i++)
#pragma unroll
                for (int j = 0; j < 4; j++) mma_tf32(acc[i][j], a[i], b[j]);
        }
    }

    // ---- epilogue: acc -> smem, 2-threads-per-row LN, coalesced store ----
    __syncthreads();
    float* epi = sm;
#pragma unroll
    for (int i = 0; i < 4; i++) {
#pragma unroll
        for (int j = 0; j < 4; j++) {
            int row = wm * 64 + i * 16 + (lane >> 2);
            int col = wn * 32 + j * 8 + (lane & 3) * 2;
            epi[row * EPS_T + col] = acc[i][j][0];
            epi[row * EPS_T + col + 1] = acc[i][j][1];
            epi[(row + 8) * EPS_T + col] = acc[i][j][2];
            epi[(row + 8) * EPS_T + col + 1] = acc[i][j][3];
        }
    }
    __syncthreads();

    const float inv3 = 1.f / 3.f;
    const float invD = 1.f / 128.f;
    {
        int r = tid >> 1;
        int h = (tid & 1) * 64;
        float s1 = 0.f, s2 = 0.f;
#pragma unroll 4
        for (int c = h; c < h + 64; c++) {
            float v = epi[r * EPS_T + c] * inv3 + spar[c];
            if (layer == 0) v = fmaxf(v, 0.f);
            epi[r * EPS_T + c] = v;
            s1 += v;
            s2 += v * v;
        }
        s1 += __shfl_xor_sync(0xffffffff, s1, 1);
        s2 += __shfl_xor_sync(0xffffffff, s2, 1);
        float mu = s1 * invD;
        float var = fmaxf(s2 * invD - mu * mu, 0.f);
        float rstd = rsqrtf(var + LN_EPS);
#pragma unroll 4
        for (int c = h; c < h + 64; c++) {
            float v = epi[r * EPS_T + c];
            epi[r * EPS_T + c] = (v - mu) * rstd * spar[128 + c] + spar[256 + c];
        }
    }
    __syncthreads();

    for (int idx = tid; idx < 128 * 32; idx += 256) {
        int r = idx >> 5, c4 = idx & 31;
        int node = row0 + r;
        if (node < NN) {
            const float* p = &epi[r * EPS_T + c4 * 4];
            ((float4*)out)[(size_t)node * 32 + c4] =
                make_float4(p[0], p[1], p[2], p[3]);
        }
    }
}

// ================= launch =================
extern "C" void kernel_launch(void* const* d_in, const int* in_sizes, int n_in,
                              void* d_out, int out_size) {
    const float* x_typeA = (const float*)d_in[0];
    const float* W_mlp   = (const float*)d_in[1];
    const float* b_mlp   = (const float*)d_in[2];
    const float* emb_B   = (const float*)d_in[3];
    const float* rel0    = (const float*)d_in[4];
    const float* lrel0   = (const float*)d_in[5];
    const float* wloop0  = (const float*)d_in[6];
    const float* win0    = (const float*)d_in[7];
    const float* wout0   = (const float*)d_in[8];
    const float* bias0   = (const float*)d_in[9];
    const float* lng0    = (const float*)d_in[10];
    const float* lnb0    = (const float*)d_in[11];
    const float* rel1    = (const float*)d_in[12];
    const float* lrel1   = (const float*)d_in[13];
    const float* wloop1  = (const float*)d_in[14];
    const float* win1    = (const float*)d_in[15];
    const float* wout1   = (const float*)d_in[16];
    const float* bias1   = (const float*)d_in[17];
    const float* lng1    = (const float*)d_in[18];
    const float* lnb1    = (const float*)d_in[19];
    const int*   esrc    = (const int*)d_in[20];
    const int*   erel    = (const int*)d_in[21];
    const int*   edst    = (const int*)d_in[22];
    float* out = (float*)d_out;

    cudaFuncSetAttribute(k_mlp_mma, cudaFuncAttributeMaxDynamicSharedMemorySize, SMF_MMA);
    cudaFuncSetAttribute(k_fused_mma, cudaFuncAttributeMaxDynamicSharedMemorySize, SMF_MMA);

    const int nScanBlk = (NN + 511) / 512;   // 196
    const int nMmaBlk = (NN + 127) / 128;    // 782
    const int nMlpBlk = (NA + 127) / 128;    // 391

    // launch #4 = k_mlp_mma (ncu-profiled)
    k_prep<<<1543, 256>>>(wout0, win0, wloop0, wout1, win1, wloop1, W_mlp, emb_B);
    k_hist<<<(NE + 255) / 256, 256>>>(esrc, edst);
    k_scan1<<<nScanBlk, 512>>>();
    k_mlp_mma<<<nMlpBlk, 256, SMF_MMA>>>(x_typeA, b_mlp);
    k_scan2<<<1, 256>>>(nScanBlk);
    k_scan3<<<nScanBlk, 512>>>();
    k_fill<<<(NE + 255) / 256, 256>>>(esrc, erel, edst);

    k_gather<<<NN / 32, 256>>>(0, rel0);
    k_fused_mma<<<nMmaBlk, 256, SMF_MMA>>>(0, lrel0, bias0, lng0, lnb0, out);
    k_gather<<<NN / 32, 256>>>(1, rel1);
    k_fused_mma<<<nMmaBlk, 256, SMF_MMA>>>(1, lrel1, bias1, lng1, lnb1, out);
}